// round 11
// baseline (speedup 1.0000x reference)
#include <cuda_runtime.h>
#include <cuda_bf16.h>

#define BB 512
#define TT 512
#define LL 64
#define NCTA (BB / 2)                 // 2 batches per (single-warp) CTA

__device__ float g_res[BB];
__device__ unsigned int g_done = 0;   // last-CTA ticket (self-resetting)

static __device__ __forceinline__ __nv_bfloat162 asbf2(unsigned int u) {
    return *reinterpret_cast<__nv_bfloat162*>(&u);
}

__global__ void __launch_bounds__(32) crf_main_kernel(
    const float* __restrict__ emission,   // [B,T,L]
    const int*   __restrict__ target,     // [B,T]
    const float* __restrict__ mask,       // [B,T]
    const float* __restrict__ start_trans,// [L]
    const float* __restrict__ trans,      // [L,L]
    const float* __restrict__ end_trans,  // [L]
    float* __restrict__ out)
{
    __shared__ __align__(16) float4 sm_me[TT];            // (mX,eX,mY,eY)
    __shared__ __align__(16) unsigned int sm_p[2][2][LL]; // [buf][batch][dup bf16x2]
    __shared__ unsigned int sm_last;

    const int lane = threadIdx.x;                 // labels 2l, 2l+1
    const int bX = blockIdx.x * 2;
    const int bY = bX + 1;

    const float*  embX  = emission + (size_t)bX * TT * LL;
    const float*  embY  = emission + (size_t)bY * TT * LL;
    const float2* emb2X = (const float2*)embX;
    const float2* emb2Y = (const float2*)embY;
    const float*  mrX   = mask + (size_t)bX * TT;
    const float*  mrY   = mask + (size_t)bY * TT;

    // stage (mask, endmask) for both batches
    for (int t = lane; t < TT; t += 32) {
        float mX  = mrX[t];
        float mY  = mrY[t];
        float nmX = (t + 1 < TT) ? mrX[t + 1] : 0.0f;
        float nmY = (t + 1 < TT) ? mrY[t + 1] : 0.0f;
        sm_me[t] = make_float4(mX, (mX > nmX) ? 1.0f : 0.0f,
                               mY, (mY > nmY) ? 1.0f : 0.0f);
    }

    // E columns 2l, 2l+1 packed bf16x2 (shared across both batches)
    __nv_bfloat162 Ep[LL];
    #pragma unroll
    for (int i = 0; i < LL; i++) {
        const float2 tr = ((const float2*)trans)[i * 32 + lane];
        Ep[i] = __floats2bfloat162_rn(__expf(tr.x), __expf(tr.y));
    }
    __syncwarp();

    // ---------------- path scores (both batches) ----------------
    float pX = 0.0f, pY = 0.0f;
    {
        const int* tgX = target + (size_t)bX * TT;
        const int* tgY = target + (size_t)bY * TT;
        for (int t = 1 + lane; t < TT; t += 32) {
            const float4 me = sm_me[t];
            const int tpX = tgX[t - 1], tcX = tgX[t];
            const int tpY = tgY[t - 1], tcY = tgY[t];
            pX += me.x * (trans[tpX * LL + tcX] + embX[(size_t)t * LL + tcX])
                + me.y * end_trans[tcX];
            pY += me.z * (trans[tpY * LL + tcY] + embY[(size_t)t * LL + tcY])
                + me.w * end_trans[tcY];
        }
        if (lane == 0) {
            pX += start_trans[tgX[0]] + embX[tgX[0]];
            pY += start_trans[tgY[0]] + embY[tgY[0]];
        }
        #pragma unroll
        for (int o = 16; o; o >>= 1) {
            pX += __shfl_xor_sync(0xffffffffu, pX, o);
            pY += __shfl_xor_sync(0xffffffffu, pY, o);
        }
    }
    const float pathX = pX, pathY = pY;

    // ---------------- forward recursions (2 independent chains) ------------
    const float2 st2 = ((const float2*)start_trans)[lane];
    const float2 et2 = ((const float2*)end_trans)[lane];
    const float2 eX0 = emb2X[lane];
    const float2 eY0 = emb2Y[lane];
    float sXA = st2.x + eX0.x, sXB = st2.y + eX0.y;
    float sYA = st2.x + eY0.x, sYB = st2.y + eY0.y;

    float SX = __shfl_sync(0xffffffffu, sXA, 0);
    float SY = __shfl_sync(0xffffffffu, sYA, 0);

    float2 eX1 = emb2X[1 * 32 + lane], eX2 = emb2X[2 * 32 + lane];
    float2 eY1 = emb2Y[1 * 32 + lane], eY2 = emb2Y[2 * 32 + lane];

    const __nv_bfloat162 z2 = __float2bfloat162_rn(0.0f);

    for (int t = 1; t < TT; t++) {
        const int buf = t & 1;
        const float2 ecX = eX1, ecY = eY1;
        eX1 = eX2; eY1 = eY2;
        if (t + 2 < TT) {
            eX2 = emb2X[(size_t)(t + 2) * 32 + lane];
            eY2 = emb2Y[(size_t)(t + 2) * 32 + lane];
        }

        // duplicated bf16x2 probs for both batches
        const __nv_bfloat162 dXA = __float2bfloat162_rn(__expf(sXA - SX));
        const __nv_bfloat162 dXB = __float2bfloat162_rn(__expf(sXB - SX));
        const __nv_bfloat162 dYA = __float2bfloat162_rn(__expf(sYA - SY));
        const __nv_bfloat162 dYB = __float2bfloat162_rn(__expf(sYB - SY));
        uint2 wX, wY;
        wX.x = *reinterpret_cast<const unsigned int*>(&dXA);
        wX.y = *reinterpret_cast<const unsigned int*>(&dXB);
        wY.x = *reinterpret_cast<const unsigned int*>(&dYA);
        wY.y = *reinterpret_cast<const unsigned int*>(&dYB);
        ((uint2*)sm_p[buf][0])[lane] = wX;
        ((uint2*)sm_p[buf][1])[lane] = wY;
        __syncwarp();

        // two interleaved 64-HFMA2 dots (independent chains)
        const uint4* qX = (const uint4*)sm_p[buf][0];
        const uint4* qY = (const uint4*)sm_p[buf][1];
        __nv_bfloat162 x0 = z2, x1 = z2, x2 = z2, x3 = z2;
        __nv_bfloat162 x4 = z2, x5 = z2, x6 = z2, x7 = z2;
        __nv_bfloat162 y0 = z2, y1 = z2, y2 = z2, y3 = z2;
        __nv_bfloat162 y4 = z2, y5 = z2, y6 = z2, y7 = z2;
        #pragma unroll
        for (int k = 0; k < 8; k++) {
            const uint4 uX = qX[2 * k];
            const uint4 vX = qX[2 * k + 1];
            const uint4 uY = qY[2 * k];
            const uint4 vY = qY[2 * k + 1];
            x0 = __hfma2(asbf2(uX.x), Ep[8 * k + 0], x0);
            y0 = __hfma2(asbf2(uY.x), Ep[8 * k + 0], y0);
            x1 = __hfma2(asbf2(uX.y), Ep[8 * k + 1], x1);
            y1 = __hfma2(asbf2(uY.y), Ep[8 * k + 1], y1);
            x2 = __hfma2(asbf2(uX.z), Ep[8 * k + 2], x2);
            y2 = __hfma2(asbf2(uY.z), Ep[8 * k + 2], y2);
            x3 = __hfma2(asbf2(uX.w), Ep[8 * k + 3], x3);
            y3 = __hfma2(asbf2(uY.w), Ep[8 * k + 3], y3);
            x4 = __hfma2(asbf2(vX.x), Ep[8 * k + 4], x4);
            y4 = __hfma2(asbf2(vY.x), Ep[8 * k + 4], y4);
            x5 = __hfma2(asbf2(vX.y), Ep[8 * k + 5], x5);
            y5 = __hfma2(asbf2(vY.y), Ep[8 * k + 5], y5);
            x6 = __hfma2(asbf2(vX.z), Ep[8 * k + 6], x6);
            y6 = __hfma2(asbf2(vY.z), Ep[8 * k + 6], y6);
            x7 = __hfma2(asbf2(vX.w), Ep[8 * k + 7], x7);
            y7 = __hfma2(asbf2(vY.w), Ep[8 * k + 7], y7);
        }
        // fp32 combine trees
        float fa = __low2float(x0) + __low2float(x4);
        float fb = __low2float(x1) + __low2float(x5);
        float fc = __low2float(x2) + __low2float(x6);
        float fd = __low2float(x3) + __low2float(x7);
        float ga = __high2float(x0) + __high2float(x4);
        float gb = __high2float(x1) + __high2float(x5);
        float gc = __high2float(x2) + __high2float(x6);
        float gd = __high2float(x3) + __high2float(x7);
        const float dotXA = (fa + fb) + (fc + fd);
        const float dotXB = (ga + gb) + (gc + gd);
        float ha = __low2float(y0) + __low2float(y4);
        float hb = __low2float(y1) + __low2float(y5);
        float hc = __low2float(y2) + __low2float(y6);
        float hd = __low2float(y3) + __low2float(y7);
        float ia = __high2float(y0) + __high2float(y4);
        float ib = __high2float(y1) + __high2float(y5);
        float ic = __high2float(y2) + __high2float(y6);
        float id = __high2float(y3) + __high2float(y7);
        const float dotYA = (ha + hb) + (hc + hd);
        const float dotYB = (ia + ib) + (ic + id);

        const float4 me = sm_me[t];
        const float nxtXA = SX + __logf(dotXA) + ecX.x;
        const float nxtXB = SX + __logf(dotXB) + ecX.y;
        const float nxtYA = SY + __logf(dotYA) + ecY.x;
        const float nxtYB = SY + __logf(dotYB) + ecY.y;
        sXA = me.x * nxtXA + (1.0f - me.x) * sXA + me.y * et2.x;
        sXB = me.x * nxtXB + (1.0f - me.x) * sXB + me.y * et2.y;
        sYA = me.z * nxtYA + (1.0f - me.z) * sYA + me.w * et2.x;
        sYB = me.z * nxtYB + (1.0f - me.z) * sYB + me.w * et2.y;

        SX = __shfl_sync(0xffffffffu, sXA, 0);
        SY = __shfl_sync(0xffffffffu, sYA, 0);
    }

    // normalizers (exact fp32 logsumexp; once)
    float wmX = fmaxf(sXA, sXB);
    float wmY = fmaxf(sYA, sYB);
    #pragma unroll
    for (int o = 16; o; o >>= 1) {
        wmX = fmaxf(wmX, __shfl_xor_sync(0xffffffffu, wmX, o));
        wmY = fmaxf(wmY, __shfl_xor_sync(0xffffffffu, wmY, o));
    }
    float peX = __expf(sXA - wmX) + __expf(sXB - wmX);
    float peY = __expf(sYA - wmY) + __expf(sYB - wmY);
    #pragma unroll
    for (int o = 16; o; o >>= 1) {
        peX += __shfl_xor_sync(0xffffffffu, peX, o);
        peY += __shfl_xor_sync(0xffffffffu, peY, o);
    }

    // ---------------- fused deterministic finalization ----------------
    if (lane == 0) {
        g_res[bX] = wmX + __logf(peX) - pathX;
        g_res[bY] = wmY + __logf(peY) - pathY;
        __threadfence();
        sm_last = atomicAdd(&g_done, 1u);        // NCTA-1 for the last CTA
    }
    __syncwarp();
    if (sm_last == NCTA - 1) {
        __threadfence();                         // acquire all g_res
        float acc = 0.0f;
        #pragma unroll
        for (int k = 0; k < BB / 32; k++) acc += g_res[lane + k * 32];
        #pragma unroll
        for (int o = 16; o; o >>= 1) acc += __shfl_xor_sync(0xffffffffu, acc, o);
        if (lane == 0) {
            out[0] = acc * (1.0f / BB);
            g_done = 0;                          // reset for graph replay
        }
    }
}

extern "C" void kernel_launch(void* const* d_in, const int* in_sizes, int n_in,
                              void* d_out, int out_size) {
    const float* emission    = (const float*)d_in[0];
    const int*   target      = (const int*)  d_in[1];
    const float* mask        = (const float*)d_in[2];
    const float* start_trans = (const float*)d_in[3];
    const float* trans       = (const float*)d_in[4];
    const float* end_trans   = (const float*)d_in[5];
    float* out = (float*)d_out;

    crf_main_kernel<<<NCTA, 32>>>(emission, target, mask, start_trans, trans,
                                  end_trans, out);
}

// round 12
// speedup vs baseline: 1.7407x; 1.7407x over previous
#include <cuda_runtime.h>
#include <cuda_bf16.h>

#define BB 512
#define TT 512
#define LL 64

__device__ float g_res[BB];
__device__ unsigned int g_done = 0;   // last-CTA ticket (self-resetting)

static __device__ __forceinline__ __nv_bfloat162 asbf2(unsigned int u) {
    return *reinterpret_cast<__nv_bfloat162*>(&u);
}

__global__ void __launch_bounds__(32) crf_main_kernel(
    const float* __restrict__ emission,   // [B,T,L]
    const int*   __restrict__ target,     // [B,T]
    const float* __restrict__ mask,       // [B,T]
    const float* __restrict__ start_trans,// [L]
    const float* __restrict__ trans,      // [L,L]
    const float* __restrict__ end_trans,  // [L]
    float* __restrict__ out)
{
    __shared__ float2 sm_me[TT];                       // (mask, endmask)
    __shared__ __align__(16) unsigned int sm_p[2][32]; // i-packed bf16x2 probs
    __shared__ float sm_s[2];                          // lane0's s (shift src)
    __shared__ unsigned int sm_last;

    const int b    = blockIdx.x;
    const int lane = threadIdx.x;                // owns labels 2l, 2l+1

    const float*  emb  = emission + (size_t)b * TT * LL;
    const float2* emb2 = (const float2*)emb;     // idx: t*32 + lane
    const int*    tgt  = target   + (size_t)b * TT;
    const float*  mrow = mask     + (size_t)b * TT;

    // stage (mask, end_mask)
    for (int t = lane; t < TT; t += 32) {
        float m  = mrow[t];
        float nm = (t + 1 < TT) ? mrow[t + 1] : 0.0f;
        sm_me[t] = make_float2(m, (m > nm) ? 1.0f : 0.0f);
    }

    // i-packed E columns for labels jA=2l, jB=2l+1:
    //   EpA[k] = (E[2k][jA], E[2k+1][jA]),  EpB[k] = (E[2k][jB], E[2k+1][jB])
    __nv_bfloat162 EpA[32], EpB[32];
    #pragma unroll
    for (int k = 0; k < 32; k++) {
        const float2 r0 = ((const float2*)trans)[(2 * k)     * 32 + lane];
        const float2 r1 = ((const float2*)trans)[(2 * k + 1) * 32 + lane];
        EpA[k] = __floats2bfloat162_rn(__expf(r0.x), __expf(r1.x));
        EpB[k] = __floats2bfloat162_rn(__expf(r0.y), __expf(r1.y));
    }
    __syncwarp();

    // ---------------- path score: parallel reduction over t ----------------
    float pacc = 0.0f;
    for (int t = 1 + lane; t < TT; t += 32) {
        const int    tp = tgt[t - 1];
        const int    tc = tgt[t];
        const float2 me = sm_me[t];
        pacc += me.x * (trans[tp * LL + tc] + emb[(size_t)t * LL + tc])
              + me.y * end_trans[tc];
    }
    if (lane == 0) {
        const int t0 = tgt[0];
        pacc += start_trans[t0] + emb[t0];
    }
    #pragma unroll
    for (int o = 16; o; o >>= 1) pacc += __shfl_xor_sync(0xffffffffu, pacc, o);
    const float path_score = pacc;

    // ---------------- forward recursion ----------------
    const float2 st2 = ((const float2*)start_trans)[lane];
    const float2 et2 = ((const float2*)end_trans)[lane];
    const float2 em0 = emb2[lane];
    float sA = st2.x + em0.x;                    // t = 0 scores
    float sB = st2.y + em0.y;

    float S = __shfl_sync(0xffffffffu, sA, 0);   // initial uniform shift

    float2 em1 = emb2[1 * 32 + lane];            // prefetch distance 2
    float2 em2 = emb2[2 * 32 + lane];

    const __nv_bfloat162 z2 = __float2bfloat162_rn(0.0f);

    for (int t = 1; t < TT; t++) {
        const int    buf    = t & 1;
        const float2 em_cur = em1;
        em1 = em2;
        if (t + 2 < TT) em2 = emb2[(size_t)(t + 2) * 32 + lane];

        // i-packed probs: lane l publishes (p_{2l}, p_{2l+1})
        if (lane == 0) sm_s[buf] = sA;           // next iteration's shift
        const __nv_bfloat162 w =
            __floats2bfloat162_rn(__expf(sA - S), __expf(sB - S));
        sm_p[buf][lane] = *reinterpret_cast<const unsigned int*>(&w);
        __syncwarp();

        // S for next iter: LDS (overlaps the p loads; off the math chain)
        const float Snxt = sm_s[buf];

        // dot over i for both labels: 64 HFMA2 (i-pairs), 8 accs/label
        const uint4* q = (const uint4*)sm_p[buf];    // 8 LDS.128
        __nv_bfloat162 a0 = z2, a1 = z2, a2 = z2, a3 = z2;
        __nv_bfloat162 a4 = z2, a5 = z2, a6 = z2, a7 = z2;
        __nv_bfloat162 c0 = z2, c1 = z2, c2 = z2, c3 = z2;
        __nv_bfloat162 c4 = z2, c5 = z2, c6 = z2, c7 = z2;
        #pragma unroll
        for (int k = 0; k < 8; k++) {
            const uint4 u = q[k];
            const __nv_bfloat162 q0 = asbf2(u.x);
            const __nv_bfloat162 q1 = asbf2(u.y);
            const __nv_bfloat162 q2 = asbf2(u.z);
            const __nv_bfloat162 q3 = asbf2(u.w);
            a0 = __hfma2(q0, EpA[4 * k + 0], a0);
            c0 = __hfma2(q0, EpB[4 * k + 0], c0);
            a1 = __hfma2(q1, EpA[4 * k + 1], a1);
            c1 = __hfma2(q1, EpB[4 * k + 1], c1);
            a2 = __hfma2(q2, EpA[4 * k + 2], a2);
            c2 = __hfma2(q2, EpB[4 * k + 2], c2);
            a3 = __hfma2(q3, EpA[4 * k + 3], a3);
            c3 = __hfma2(q3, EpB[4 * k + 3], c3);
            // second half of the 32 k's handled by rotating acc banks
            (void)a4; (void)a5; (void)a6; (void)a7;
            (void)c4; (void)c5; (void)c6; (void)c7;
        }
        #pragma unroll
        for (int k = 8; k < 8; k++) {}           // (loop fully covers k via 4*k)
        // NOTE: loop above covers k=0..7 with 4 i-pairs each = 32 i-pairs total.

        // bf16 hadd2 trees -> fp32 horizontal sum
        const __nv_bfloat162 tA =
            __hadd2(__hadd2(a0, a1), __hadd2(a2, a3));
        const __nv_bfloat162 tB =
            __hadd2(__hadd2(c0, c1), __hadd2(c2, c3));
        const float dotA = __low2float(tA) + __high2float(tA);
        const float dotB = __low2float(tB) + __high2float(tB);

        const float2 me  = sm_me[t];
        const float nxtA = S + __logf(dotA) + em_cur.x;
        const float nxtB = S + __logf(dotB) + em_cur.y;
        sA = sA + me.x * (nxtA - sA) + me.y * et2.x;
        sB = sB + me.x * (nxtB - sB) + me.y * et2.y;

        S = Snxt;
    }

    // normalizer = logsumexp over 64 labels (exact fp32; once)
    float wm = fmaxf(sA, sB);
    #pragma unroll
    for (int o = 16; o; o >>= 1) wm = fmaxf(wm, __shfl_xor_sync(0xffffffffu, wm, o));
    float pe = __expf(sA - wm) + __expf(sB - wm);
    #pragma unroll
    for (int o = 16; o; o >>= 1) pe += __shfl_xor_sync(0xffffffffu, pe, o);

    // ---------------- fused deterministic finalization ----------------
    if (lane == 0) {
        const float norm = wm + __logf(pe);
        g_res[b] = norm - path_score;
        __threadfence();
        sm_last = atomicAdd(&g_done, 1u);        // BB-1 for the last CTA
    }
    __syncwarp();
    if (sm_last == BB - 1) {
        __threadfence();                         // acquire all g_res
        float acc = 0.0f;
        #pragma unroll
        for (int k = 0; k < BB / 32; k++) acc += g_res[lane + k * 32];
        #pragma unroll
        for (int o = 16; o; o >>= 1) acc += __shfl_xor_sync(0xffffffffu, acc, o);
        if (lane == 0) {
            out[0] = acc * (1.0f / BB);
            g_done = 0;                          // reset for graph replay
        }
    }
}

extern "C" void kernel_launch(void* const* d_in, const int* in_sizes, int n_in,
                              void* d_out, int out_size) {
    const float* emission    = (const float*)d_in[0];
    const int*   target      = (const int*)  d_in[1];
    const float* mask        = (const float*)d_in[2];
    const float* start_trans = (const float*)d_in[3];
    const float* trans       = (const float*)d_in[4];
    const float* end_trans   = (const float*)d_in[5];
    float* out = (float*)d_out;

    crf_main_kernel<<<BB, 32>>>(emission, target, mask, start_trans, trans,
                                end_trans, out);
}